// round 15
// baseline (speedup 1.0000x reference)
#include <cuda_runtime.h>
#include <cuda_bf16.h>
#include <cstdint>

#define N_NODES 50000
#define N_EDGES 800000
#define DIM 96
#define N_LAYERS 4
#define N_GRAPHS 256
#define BN_EPS 1e-5f
#define SCAN_BLOCKS ((N_NODES + 255) / 256)   // 196
#define GATHER_BLOCKS 1184                    // 148 SMs * 8
#define NKT 12                                // k-tiles (96/8)
#define NNT 12                                // n-tiles (96/8)
#define BFRAG_PER_LAYER (NKT * NNT * 32 * 2)  // 9216 uint32

// ---------------- device scratch (no allocations allowed) ----------------
__device__ float g_hw[N_NODES * DIM];     // (h @ W) * dis[row]  (fp32)
__device__ float g_agg[N_NODES * DIM];    // layer output pre-BN
__device__ float g_dis[N_NODES];          // 1/sqrt(deg)
__device__ int   g_count[N_NODES];
__device__ int   g_off[N_NODES + 1];
__device__ int   g_cursor[N_NODES];
__device__ int   g_csr_src[N_EDGES];
__device__ int   g_bsum[SCAN_BLOCKS];
__device__ int   g_bpre[SCAN_BLOCKS];
__device__ float g_part[2 * DIM * GATHER_BLOCKS];  // per-block BN partials
__device__ float g_bn[2 * DIM];           // BN affine: a, c  (y = a*x + c)
__device__ float g_cnt[N_GRAPHS];
__device__ unsigned g_done = 0;
__device__ uint32_t g_bfrag[N_LAYERS * BFRAG_PER_LAYER];  // pre-packed tf32 B frags

__device__ __forceinline__ uint32_t f32_to_tf32(float f) {
    uint32_t r;
    asm("cvt.rna.tf32.f32 %0, %1;" : "=r"(r) : "f"(f));
    return r;
}

// ---------------- init ----------------
__global__ void init_kernel(float* out) {
    int i = blockIdx.x * blockDim.x + threadIdx.x;
    if (i < N_NODES) g_count[i] = 0;
    if (i < N_GRAPHS) g_cnt[i] = 0.0f;
    if (i < N_GRAPHS * DIM) out[i] = 0.0f;
}

// ---------------- pre-pack B fragments (all layers) ----------------
__global__ void bfrag_pack_kernel(const float* __restrict__ W) {
    int tid = blockIdx.x * blockDim.x + threadIdx.x;
    if (tid >= N_LAYERS * BFRAG_PER_LAYER) return;
    int j = tid & 1;
    int lane = (tid >> 1) & 31;
    int nt = (tid >> 6) % NNT;
    int kt = ((tid >> 6) / NNT) % NKT;
    int layer = tid / BFRAG_PER_LAYER;
    int k = kt * 8 + (lane & 3) + j * 4;
    int n = nt * 8 + (lane >> 2);
    g_bfrag[tid] = f32_to_tf32(W[layer * DIM * DIM + k * DIM + n]);
}

// ---------------- degree histogram + graph node counts ----------------
__global__ void deg_kernel(const int* __restrict__ dst, const int* __restrict__ batch) {
    int i = blockIdx.x * blockDim.x + threadIdx.x;
    int stride = gridDim.x * blockDim.x;
    for (int e = i; e < N_EDGES; e += stride)
        atomicAdd(&g_count[dst[e]], 1);
    for (int v = i; v < N_NODES; v += stride)
        atomicAdd(&g_cnt[batch[v]], 1.0f);
}

// ---------------- scan phase A ----------------
__global__ __launch_bounds__(256) void scanA_kernel() {
    __shared__ int wsum[8];
    int idx = blockIdx.x * 256 + threadIdx.x;
    int c = 0;
    if (idx < N_NODES) {
        c = g_count[idx];
        g_dis[idx] = rsqrtf((float)(c + 1));
    }
    int lane = threadIdx.x & 31, wid = threadIdx.x >> 5;
    int v = c;
#pragma unroll
    for (int o = 16; o > 0; o >>= 1) v += __shfl_down_sync(0xffffffffu, v, o);
    if (lane == 0) wsum[wid] = v;
    __syncthreads();
    if (threadIdx.x == 0) {
        int s = 0;
#pragma unroll
        for (int w = 0; w < 8; w++) s += wsum[w];
        g_bsum[blockIdx.x] = s;
    }
}

// ---------------- scan phase B ----------------
__global__ __launch_bounds__(256) void scanB_kernel() {
    __shared__ int wsum[8];
    int t = threadIdx.x;
    int v = (t < SCAN_BLOCKS) ? g_bsum[t] : 0;
    int lane = t & 31, wid = t >> 5;
    int inc = v;
#pragma unroll
    for (int o = 1; o < 32; o <<= 1) {
        int n = __shfl_up_sync(0xffffffffu, inc, o);
        if (lane >= o) inc += n;
    }
    if (lane == 31) wsum[wid] = inc;
    __syncthreads();
    if (wid == 0 && lane < 8) {
        int w = wsum[lane];
#pragma unroll
        for (int o = 1; o < 8; o <<= 1) {
            int n = __shfl_up_sync(0xffu, w, o);
            if (lane >= o) w += n;
        }
        wsum[lane] = w;
    }
    __syncthreads();
    int incl = inc + (wid > 0 ? wsum[wid - 1] : 0);
    if (t < SCAN_BLOCKS) g_bpre[t] = incl - v;
    if (t == 255) g_off[N_NODES] = wsum[7];
}

// ---------------- scan phase C ----------------
__global__ __launch_bounds__(256) void scanC_kernel() {
    __shared__ int wsum[8];
    int idx = blockIdx.x * 256 + threadIdx.x;
    int c = (idx < N_NODES) ? g_count[idx] : 0;
    int lane = threadIdx.x & 31, wid = threadIdx.x >> 5;
    int inc = c;
#pragma unroll
    for (int o = 1; o < 32; o <<= 1) {
        int n = __shfl_up_sync(0xffffffffu, inc, o);
        if (lane >= o) inc += n;
    }
    if (lane == 31) wsum[wid] = inc;
    __syncthreads();
    if (wid == 0 && lane < 8) {
        int w = wsum[lane];
#pragma unroll
        for (int o = 1; o < 8; o <<= 1) {
            int n = __shfl_up_sync(0xffu, w, o);
            if (lane >= o) w += n;
        }
        wsum[lane] = w;
    }
    __syncthreads();
    int excl = inc - c + (wid > 0 ? wsum[wid - 1] : 0) + g_bpre[blockIdx.x];
    if (idx < N_NODES) {
        g_off[idx] = excl;
        g_cursor[idx] = excl;
    }
}

__global__ void csr_fill_kernel(const int* __restrict__ src, const int* __restrict__ dst) {
    int e = blockIdx.x * blockDim.x + threadIdx.x;
    if (e < N_EDGES) {
        int d = dst[e];
        int pos = atomicAdd(&g_cursor[d], 1);
        g_csr_src[pos] = src[e];
    }
}

// ---------------- tf32 mma.sync GEMM (champion, unchanged) ----------------
#define A_STRIDE 100
#define MMA_SMEM ((128 * A_STRIDE + BFRAG_PER_LAYER) * 4)   // 88064 B

__global__ __launch_bounds__(256) void mma_gemm_kernel(const float* __restrict__ in,
                                                       const uint32_t* __restrict__ bfrag,
                                                       int apply_bn) {
    extern __shared__ uint32_t smem[];
    uint32_t* As = smem;                       // [128][100]
    uint32_t* Bs = smem + 128 * A_STRIDE;      // [9216]

    int t = threadIdx.x;
    int row0 = blockIdx.x * 128;

    const float* __restrict__ inp = apply_bn ? g_agg : in;
    for (int i = t; i < 128 * DIM; i += 256) {
        int r = i / DIM, c = i % DIM;
        int rr = row0 + r;
        float v = (rr < N_NODES) ? inp[(size_t)rr * DIM + c] : 0.0f;
        if (apply_bn) v = fmaxf(fmaf(v, g_bn[c], g_bn[DIM + c]), 0.0f);
        As[r * A_STRIDE + c] = f32_to_tf32(v);
    }
    for (int i = t; i < BFRAG_PER_LAYER / 4; i += 256)
        *(uint4*)&Bs[i * 4] = *(const uint4*)&bfrag[i * 4];
    __syncthreads();

    int lane = t & 31, wid = t >> 5;
    int gid = lane >> 2, tig = lane & 3;
    int wr = wid * 16;

    float acc[NNT][4];
#pragma unroll
    for (int n = 0; n < NNT; n++)
#pragma unroll
        for (int q = 0; q < 4; q++) acc[n][q] = 0.0f;

#pragma unroll
    for (int kt = 0; kt < NKT; kt++) {
        int abase = (wr + gid) * A_STRIDE + kt * 8 + tig;
        uint32_t a0 = As[abase];
        uint32_t a2 = As[abase + 4];
        uint32_t a1 = As[abase + 8 * A_STRIDE];
        uint32_t a3 = As[abase + 8 * A_STRIDE + 4];
#pragma unroll
        for (int nt = 0; nt < NNT; nt++) {
            uint2 b = *(const uint2*)&Bs[((kt * NNT + nt) * 32 + lane) * 2];
            asm volatile(
                "mma.sync.aligned.m16n8k8.row.col.f32.tf32.tf32.f32 "
                "{%0,%1,%2,%3}, {%4,%5,%6,%7}, {%8,%9}, {%0,%1,%2,%3};"
                : "+f"(acc[nt][0]), "+f"(acc[nt][1]),
                  "+f"(acc[nt][2]), "+f"(acc[nt][3])
                : "r"(a0), "r"(a1), "r"(a2), "r"(a3), "r"(b.x), "r"(b.y));
        }
    }

    int r0 = row0 + wr + gid;
    int r1 = r0 + 8;
    if (r0 < N_NODES) {
        float dv = g_dis[r0];
        float* op = &g_hw[(size_t)r0 * DIM];
#pragma unroll
        for (int nt = 0; nt < NNT; nt++)
            *(float2*)(op + nt * 8 + tig * 2) =
                make_float2(acc[nt][0] * dv, acc[nt][1] * dv);
    }
    if (r1 < N_NODES) {
        float dv = g_dis[r1];
        float* op = &g_hw[(size_t)r1 * DIM];
#pragma unroll
        for (int nt = 0; nt < NNT; nt++)
            *(float2*)(op + nt * 8 + tig * 2) =
                make_float2(acc[nt][2] * dv, acc[nt][3] * dv);
    }
}

// ---------------- gather: champion body; BN stats via per-block partials -----
__global__ __launch_bounds__(256) void gather_kernel(const float* __restrict__ bl,
                                                     const float* __restrict__ gamma,
                                                     const float* __restrict__ beta) {
    __shared__ float ssum[DIM], ssq[DIM];
    __shared__ float fin[2 * DIM];
    __shared__ bool s_last;
    int t = threadIdx.x;
    if (t < DIM) { ssum[t] = 0.0f; ssq[t] = 0.0f; }
    __syncthreads();

    int lane = t & 31, warp = t >> 5;
    int gwarp = blockIdx.x * 8 + warp;
    const int TOT_WARPS = GATHER_BLOCKS * 8;
    const unsigned FULL = 0xffffffffu;
    bool datal = (lane < 24);
    int col = (datal ? lane : 0) * 4;

    float4 b4 = *(const float4*)&bl[col];
    float4 st = make_float4(0.f, 0.f, 0.f, 0.f);
    float4 sq = make_float4(0.f, 0.f, 0.f, 0.f);

    for (int node = gwarp; node < N_NODES; node += TOT_WARPS) {
        int roff = g_off[node];
        int rend = g_off[node + 1];
        float4 acc = make_float4(0.f, 0.f, 0.f, 0.f);

        for (int base = roff; base < rend; base += 32) {
            int nh = rend - base; if (nh > 32) nh = 32;
            int myidx = (lane < nh) ? g_csr_src[base + lane] : 0;
            int jj = 0;
            for (; jj + 4 <= nh; jj += 4) {
                int s0 = __shfl_sync(FULL, myidx, jj);
                int s1 = __shfl_sync(FULL, myidx, jj + 1);
                int s2 = __shfl_sync(FULL, myidx, jj + 2);
                int s3 = __shfl_sync(FULL, myidx, jj + 3);
                if (datal) {
                    float4 v0 = *(const float4*)&g_hw[(size_t)s0 * DIM + col];
                    float4 v1 = *(const float4*)&g_hw[(size_t)s1 * DIM + col];
                    float4 v2 = *(const float4*)&g_hw[(size_t)s2 * DIM + col];
                    float4 v3 = *(const float4*)&g_hw[(size_t)s3 * DIM + col];
                    acc.x += (v0.x + v1.x) + (v2.x + v3.x);
                    acc.y += (v0.y + v1.y) + (v2.y + v3.y);
                    acc.z += (v0.z + v1.z) + (v2.z + v3.z);
                    acc.w += (v0.w + v1.w) + (v2.w + v3.w);
                }
            }
            for (; jj < nh; jj++) {
                int s0 = __shfl_sync(FULL, myidx, jj);
                if (datal) {
                    float4 v0 = *(const float4*)&g_hw[(size_t)s0 * DIM + col];
                    acc.x += v0.x; acc.y += v0.y; acc.z += v0.z; acc.w += v0.w;
                }
            }
        }

        if (datal) {
            float4 vs = *(const float4*)&g_hw[(size_t)node * DIM + col];
            acc.x += vs.x; acc.y += vs.y; acc.z += vs.z; acc.w += vs.w;

            float dd = g_dis[node];
            float4 r;
            r.x = fmaf(acc.x, dd, b4.x);
            r.y = fmaf(acc.y, dd, b4.y);
            r.z = fmaf(acc.z, dd, b4.z);
            r.w = fmaf(acc.w, dd, b4.w);
            *(float4*)&g_agg[(size_t)node * DIM + col] = r;

            st.x += r.x; st.y += r.y; st.z += r.z; st.w += r.w;
            sq.x = fmaf(r.x, r.x, sq.x); sq.y = fmaf(r.y, r.y, sq.y);
            sq.z = fmaf(r.z, r.z, sq.z); sq.w = fmaf(r.w, r.w, sq.w);
        }
    }
    if (datal) {
        atomicAdd(&ssum[col + 0], st.x); atomicAdd(&ssum[col + 1], st.y);
        atomicAdd(&ssum[col + 2], st.z); atomicAdd(&ssum[col + 3], st.w);
        atomicAdd(&ssq[col + 0], sq.x);  atomicAdd(&ssq[col + 1], sq.y);
        atomicAdd(&ssq[col + 2], sq.z);  atomicAdd(&ssq[col + 3], sq.w);
    }
    __syncthreads();
    // per-block partials: plain stores, no contended atomics
    if (t < 2 * DIM) {
        float v = (t < DIM) ? ssum[t] : ssq[t - DIM];
        g_part[t * GATHER_BLOCKS + blockIdx.x] = v;
    }

    // ---- last-block BN finalize: sum 1184 partials per stat column ----
    __threadfence();
    __syncthreads();
    if (t == 0) {
        unsigned v = atomicAdd(&g_done, 1u);
        s_last = (v == (unsigned)(gridDim.x - 1));
    }
    __syncthreads();
    if (s_last) {
        if (t < 2 * DIM) {
            const float4* p = (const float4*)&g_part[t * GATHER_BLOCKS];
            float s = 0.0f;
#pragma unroll 4
            for (int j = 0; j < GATHER_BLOCKS / 4; j++) {
                float4 v = p[j];
                s += (v.x + v.y) + (v.z + v.w);
            }
            fin[t] = s;
        }
        __syncthreads();
        if (t < DIM) {
            float s  = fin[t];
            float s2 = fin[DIM + t];
            float mu  = s * (1.0f / N_NODES);
            float var = s2 * (1.0f / N_NODES) - mu * mu;
            float rs  = rsqrtf(var + BN_EPS);
            float a   = rs * gamma[t];
            g_bn[t] = a;
            g_bn[DIM + t] = beta[t] - mu * a;
        }
        if (t == 0) g_done = 0;
    }
}

// ---------------- pooling (champion, unchanged) ----------------
__global__ __launch_bounds__(384) void pool_kernel(const int* __restrict__ batch,
                                                   float* __restrict__ out) {
    int c = threadIdx.x;
    int ty = threadIdx.y;
    int r0 = blockIdx.x * 128;
    int rend = r0 + 128; if (rend > N_NODES) rend = N_NODES;
    float a = g_bn[c], cc = g_bn[DIM + c];
    float acc = 0.0f;
    int cg = -1;
    for (int r = r0 + ty; r < rend; r += 4) {
        float v = fmaxf(fmaf(g_agg[(size_t)r * DIM + c], a, cc), 0.0f);
        int g = batch[r];
        if (g != cg) {
            if (cg >= 0) atomicAdd(&out[cg * DIM + c], acc);
            cg = g; acc = 0.0f;
        }
        acc += v;
    }
    if (cg >= 0) atomicAdd(&out[cg * DIM + c], acc);
}

__global__ void pool_div_kernel(float* __restrict__ out) {
    int i = blockIdx.x * blockDim.x + threadIdx.x;
    if (i < N_GRAPHS * DIM) {
        float cnt = g_cnt[i / DIM];
        out[i] = out[i] / fmaxf(cnt, 1.0f);
    }
}

// ---------------- launch (champion structure) ----------------
extern "C" void kernel_launch(void* const* d_in, const int* in_sizes, int n_in,
                              void* d_out, int out_size) {
    const float* x     = (const float*)d_in[0];
    const int*   eidx  = (const int*)d_in[1];
    const int*   batch = (const int*)d_in[2];
    const float* W     = (const float*)d_in[3];
    const float* b     = (const float*)d_in[4];
    const float* gamma = (const float*)d_in[5];
    const float* beta  = (const float*)d_in[6];
    float* out = (float*)d_out;

    const int* src = eidx;
    const int* dst = eidx + N_EDGES;

    static cudaStream_t s1 = nullptr;
    static cudaEvent_t ev_a = nullptr, ev_csr = nullptr;
    static uint32_t* bfrag_ptr = nullptr;
    if (!s1) {
        cudaFuncSetAttribute(mma_gemm_kernel,
                             cudaFuncAttributeMaxDynamicSharedMemorySize, MMA_SMEM);
        cudaStreamCreateWithFlags(&s1, cudaStreamNonBlocking);
        cudaEventCreateWithFlags(&ev_a, cudaEventDisableTiming);
        cudaEventCreateWithFlags(&ev_csr, cudaEventDisableTiming);
        cudaGetSymbolAddress((void**)&bfrag_ptr, g_bfrag);
    }

    // main stream: bfrag pack + init + deg + scanA (dis needed by gemm epilogue)
    bfrag_pack_kernel<<<(N_LAYERS * BFRAG_PER_LAYER + 255) / 256, 256>>>(W);
    init_kernel<<<(N_NODES + 255) / 256, 256>>>(out);
    deg_kernel<<<512, 256>>>(dst, batch);
    scanA_kernel<<<SCAN_BLOCKS, 256>>>();
    cudaEventRecord(ev_a, 0);

    // side stream: finish CSR build, overlapped with layer-0 GEMM
    cudaStreamWaitEvent(s1, ev_a, 0);
    scanB_kernel<<<1, 256, 0, s1>>>();
    scanC_kernel<<<SCAN_BLOCKS, 256, 0, s1>>>();
    csr_fill_kernel<<<(N_EDGES + 255) / 256, 256, 0, s1>>>(src, dst);
    cudaEventRecord(ev_csr, s1);

    int gemm_grid = (N_NODES + 127) / 128;   // 391

    mma_gemm_kernel<<<gemm_grid, 256, MMA_SMEM>>>(x, bfrag_ptr, 0);
    cudaStreamWaitEvent(0, ev_csr, 0);

    for (int l = 0; l < N_LAYERS; l++) {
        if (l > 0)
            mma_gemm_kernel<<<gemm_grid, 256, MMA_SMEM>>>(
                x, bfrag_ptr + l * BFRAG_PER_LAYER, 1);
        gather_kernel<<<GATHER_BLOCKS, 256>>>(b + l * DIM, gamma + l * DIM,
                                              beta + l * DIM);
    }

    dim3 pool_blk(96, 4);
    pool_kernel<<<(N_NODES + 127) / 128, pool_blk>>>(batch, out);
    pool_div_kernel<<<(N_GRAPHS * DIM + 255) / 256, 256>>>(out);
}

// round 16
// speedup vs baseline: 1.4770x; 1.4770x over previous
#include <cuda_runtime.h>
#include <cuda_bf16.h>
#include <cstdint>

#define N_NODES 50000
#define N_EDGES 800000
#define DIM 96
#define N_LAYERS 4
#define N_GRAPHS 256
#define BN_EPS 1e-5f
#define SCAN_BLOCKS ((N_NODES + 255) / 256)   // 196
#define GATHER_BLOCKS 1184                    // 148 SMs * 8
#define NKT 12                                // k-tiles (96/8)
#define NNT 12                                // n-tiles (96/8)
#define BFRAG_PER_LAYER (NKT * NNT * 32 * 2)  // 9216 uint32
#define STATS_COPIES 8
#define STATS_STRIDE 512                      // floats; 2KB per copy

// ---------------- device scratch (no allocations allowed) ----------------
__device__ float g_hw[N_NODES * DIM];     // (h @ W) * dis[row]  (fp32)
__device__ float g_agg[N_NODES * DIM];    // layer output pre-BN
__device__ float g_dis[N_NODES];          // 1/sqrt(deg)
__device__ int   g_count[N_NODES];
__device__ int   g_off[N_NODES + 1];
__device__ int   g_cursor[N_NODES];
__device__ int   g_csr_src[N_EDGES];
__device__ int   g_bsum[SCAN_BLOCKS];
__device__ int   g_bpre[SCAN_BLOCKS];
__device__ float g_stats8[STATS_COPIES * STATS_STRIDE];  // striped BN stats
__device__ float g_bn[2 * DIM];           // BN affine: a, c  (y = a*x + c)
__device__ float g_cnt[N_GRAPHS];
__device__ unsigned g_done = 0;
__device__ uint32_t g_bfrag[N_LAYERS * BFRAG_PER_LAYER];  // pre-packed tf32 B frags

__device__ __forceinline__ uint32_t f32_to_tf32(float f) {
    uint32_t r;
    asm("cvt.rna.tf32.f32 %0, %1;" : "=r"(r) : "f"(f));
    return r;
}

// ---------------- init ----------------
__global__ void init_kernel(float* out) {
    int i = blockIdx.x * blockDim.x + threadIdx.x;
    if (i < N_NODES) g_count[i] = 0;
    if (i < STATS_COPIES * STATS_STRIDE) g_stats8[i] = 0.0f;
    if (i < N_GRAPHS) g_cnt[i] = 0.0f;
    if (i < N_GRAPHS * DIM) out[i] = 0.0f;
}

// ---------------- pre-pack B fragments (all layers) ----------------
__global__ void bfrag_pack_kernel(const float* __restrict__ W) {
    int tid = blockIdx.x * blockDim.x + threadIdx.x;
    if (tid >= N_LAYERS * BFRAG_PER_LAYER) return;
    int j = tid & 1;
    int lane = (tid >> 1) & 31;
    int nt = (tid >> 6) % NNT;
    int kt = ((tid >> 6) / NNT) % NKT;
    int layer = tid / BFRAG_PER_LAYER;
    int k = kt * 8 + (lane & 3) + j * 4;
    int n = nt * 8 + (lane >> 2);
    g_bfrag[tid] = f32_to_tf32(W[layer * DIM * DIM + k * DIM + n]);
}

// ---------------- degree histogram + graph node counts ----------------
__global__ void deg_kernel(const int* __restrict__ dst, const int* __restrict__ batch) {
    int i = blockIdx.x * blockDim.x + threadIdx.x;
    int stride = gridDim.x * blockDim.x;
    for (int e = i; e < N_EDGES; e += stride)
        atomicAdd(&g_count[dst[e]], 1);
    for (int v = i; v < N_NODES; v += stride)
        atomicAdd(&g_cnt[batch[v]], 1.0f);
}

// ---------------- scan phase A ----------------
__global__ __launch_bounds__(256) void scanA_kernel() {
    __shared__ int wsum[8];
    int idx = blockIdx.x * 256 + threadIdx.x;
    int c = 0;
    if (idx < N_NODES) {
        c = g_count[idx];
        g_dis[idx] = rsqrtf((float)(c + 1));
    }
    int lane = threadIdx.x & 31, wid = threadIdx.x >> 5;
    int v = c;
#pragma unroll
    for (int o = 16; o > 0; o >>= 1) v += __shfl_down_sync(0xffffffffu, v, o);
    if (lane == 0) wsum[wid] = v;
    __syncthreads();
    if (threadIdx.x == 0) {
        int s = 0;
#pragma unroll
        for (int w = 0; w < 8; w++) s += wsum[w];
        g_bsum[blockIdx.x] = s;
    }
}

// ---------------- scan phase B ----------------
__global__ __launch_bounds__(256) void scanB_kernel() {
    __shared__ int wsum[8];
    int t = threadIdx.x;
    int v = (t < SCAN_BLOCKS) ? g_bsum[t] : 0;
    int lane = t & 31, wid = t >> 5;
    int inc = v;
#pragma unroll
    for (int o = 1; o < 32; o <<= 1) {
        int n = __shfl_up_sync(0xffffffffu, inc, o);
        if (lane >= o) inc += n;
    }
    if (lane == 31) wsum[wid] = inc;
    __syncthreads();
    if (wid == 0 && lane < 8) {
        int w = wsum[lane];
#pragma unroll
        for (int o = 1; o < 8; o <<= 1) {
            int n = __shfl_up_sync(0xffu, w, o);
            if (lane >= o) w += n;
        }
        wsum[lane] = w;
    }
    __syncthreads();
    int incl = inc + (wid > 0 ? wsum[wid - 1] : 0);
    if (t < SCAN_BLOCKS) g_bpre[t] = incl - v;
    if (t == 255) g_off[N_NODES] = wsum[7];
}

// ---------------- scan phase C ----------------
__global__ __launch_bounds__(256) void scanC_kernel() {
    __shared__ int wsum[8];
    int idx = blockIdx.x * 256 + threadIdx.x;
    int c = (idx < N_NODES) ? g_count[idx] : 0;
    int lane = threadIdx.x & 31, wid = threadIdx.x >> 5;
    int inc = c;
#pragma unroll
    for (int o = 1; o < 32; o <<= 1) {
        int n = __shfl_up_sync(0xffffffffu, inc, o);
        if (lane >= o) inc += n;
    }
    if (lane == 31) wsum[wid] = inc;
    __syncthreads();
    if (wid == 0 && lane < 8) {
        int w = wsum[lane];
#pragma unroll
        for (int o = 1; o < 8; o <<= 1) {
            int n = __shfl_up_sync(0xffu, w, o);
            if (lane >= o) w += n;
        }
        wsum[lane] = w;
    }
    __syncthreads();
    int excl = inc - c + (wid > 0 ? wsum[wid - 1] : 0) + g_bpre[blockIdx.x];
    if (idx < N_NODES) {
        g_off[idx] = excl;
        g_cursor[idx] = excl;
    }
}

__global__ void csr_fill_kernel(const int* __restrict__ src, const int* __restrict__ dst) {
    int e = blockIdx.x * blockDim.x + threadIdx.x;
    if (e < N_EDGES) {
        int d = dst[e];
        int pos = atomicAdd(&g_cursor[d], 1);
        g_csr_src[pos] = src[e];
    }
}

// ---------------- tf32 mma.sync GEMM (champion, unchanged) ----------------
#define A_STRIDE 100
#define MMA_SMEM ((128 * A_STRIDE + BFRAG_PER_LAYER) * 4)   // 88064 B

__global__ __launch_bounds__(256) void mma_gemm_kernel(const float* __restrict__ in,
                                                       const uint32_t* __restrict__ bfrag,
                                                       int apply_bn) {
    extern __shared__ uint32_t smem[];
    uint32_t* As = smem;                       // [128][100]
    uint32_t* Bs = smem + 128 * A_STRIDE;      // [9216]

    int t = threadIdx.x;
    int row0 = blockIdx.x * 128;

    const float* __restrict__ inp = apply_bn ? g_agg : in;
    for (int i = t; i < 128 * DIM; i += 256) {
        int r = i / DIM, c = i % DIM;
        int rr = row0 + r;
        float v = (rr < N_NODES) ? inp[(size_t)rr * DIM + c] : 0.0f;
        if (apply_bn) v = fmaxf(fmaf(v, g_bn[c], g_bn[DIM + c]), 0.0f);
        As[r * A_STRIDE + c] = f32_to_tf32(v);
    }
    for (int i = t; i < BFRAG_PER_LAYER / 4; i += 256)
        *(uint4*)&Bs[i * 4] = *(const uint4*)&bfrag[i * 4];
    __syncthreads();

    int lane = t & 31, wid = t >> 5;
    int gid = lane >> 2, tig = lane & 3;
    int wr = wid * 16;

    float acc[NNT][4];
#pragma unroll
    for (int n = 0; n < NNT; n++)
#pragma unroll
        for (int q = 0; q < 4; q++) acc[n][q] = 0.0f;

#pragma unroll
    for (int kt = 0; kt < NKT; kt++) {
        int abase = (wr + gid) * A_STRIDE + kt * 8 + tig;
        uint32_t a0 = As[abase];
        uint32_t a2 = As[abase + 4];
        uint32_t a1 = As[abase + 8 * A_STRIDE];
        uint32_t a3 = As[abase + 8 * A_STRIDE + 4];
#pragma unroll
        for (int nt = 0; nt < NNT; nt++) {
            uint2 b = *(const uint2*)&Bs[((kt * NNT + nt) * 32 + lane) * 2];
            asm volatile(
                "mma.sync.aligned.m16n8k8.row.col.f32.tf32.tf32.f32 "
                "{%0,%1,%2,%3}, {%4,%5,%6,%7}, {%8,%9}, {%0,%1,%2,%3};"
                : "+f"(acc[nt][0]), "+f"(acc[nt][1]),
                  "+f"(acc[nt][2]), "+f"(acc[nt][3])
                : "r"(a0), "r"(a1), "r"(a2), "r"(a3), "r"(b.x), "r"(b.y));
        }
    }

    int r0 = row0 + wr + gid;
    int r1 = r0 + 8;
    if (r0 < N_NODES) {
        float dv = g_dis[r0];
        float* op = &g_hw[(size_t)r0 * DIM];
#pragma unroll
        for (int nt = 0; nt < NNT; nt++)
            *(float2*)(op + nt * 8 + tig * 2) =
                make_float2(acc[nt][0] * dv, acc[nt][1] * dv);
    }
    if (r1 < N_NODES) {
        float dv = g_dis[r1];
        float* op = &g_hw[(size_t)r1 * DIM];
#pragma unroll
        for (int nt = 0; nt < NNT; nt++)
            *(float2*)(op + nt * 8 + tig * 2) =
                make_float2(acc[nt][2] * dv, acc[nt][3] * dv);
    }
}

// ---------------- gather: champion body; BN stats striped across 8 copies ----
__global__ __launch_bounds__(256) void gather_kernel(const float* __restrict__ bl,
                                                     const float* __restrict__ gamma,
                                                     const float* __restrict__ beta) {
    __shared__ float ssum[DIM], ssq[DIM];
    __shared__ bool s_last;
    int t = threadIdx.x;
    if (t < DIM) { ssum[t] = 0.0f; ssq[t] = 0.0f; }
    __syncthreads();

    int lane = t & 31, warp = t >> 5;
    int gwarp = blockIdx.x * 8 + warp;
    const int TOT_WARPS = GATHER_BLOCKS * 8;
    const unsigned FULL = 0xffffffffu;
    bool datal = (lane < 24);
    int col = (datal ? lane : 0) * 4;

    float4 b4 = *(const float4*)&bl[col];
    float4 st = make_float4(0.f, 0.f, 0.f, 0.f);
    float4 sq = make_float4(0.f, 0.f, 0.f, 0.f);

    for (int node = gwarp; node < N_NODES; node += TOT_WARPS) {
        int roff = g_off[node];
        int rend = g_off[node + 1];
        float4 acc = make_float4(0.f, 0.f, 0.f, 0.f);

        for (int base = roff; base < rend; base += 32) {
            int nh = rend - base; if (nh > 32) nh = 32;
            int myidx = (lane < nh) ? g_csr_src[base + lane] : 0;
            int jj = 0;
            for (; jj + 4 <= nh; jj += 4) {
                int s0 = __shfl_sync(FULL, myidx, jj);
                int s1 = __shfl_sync(FULL, myidx, jj + 1);
                int s2 = __shfl_sync(FULL, myidx, jj + 2);
                int s3 = __shfl_sync(FULL, myidx, jj + 3);
                if (datal) {
                    float4 v0 = *(const float4*)&g_hw[(size_t)s0 * DIM + col];
                    float4 v1 = *(const float4*)&g_hw[(size_t)s1 * DIM + col];
                    float4 v2 = *(const float4*)&g_hw[(size_t)s2 * DIM + col];
                    float4 v3 = *(const float4*)&g_hw[(size_t)s3 * DIM + col];
                    acc.x += (v0.x + v1.x) + (v2.x + v3.x);
                    acc.y += (v0.y + v1.y) + (v2.y + v3.y);
                    acc.z += (v0.z + v1.z) + (v2.z + v3.z);
                    acc.w += (v0.w + v1.w) + (v2.w + v3.w);
                }
            }
            for (; jj < nh; jj++) {
                int s0 = __shfl_sync(FULL, myidx, jj);
                if (datal) {
                    float4 v0 = *(const float4*)&g_hw[(size_t)s0 * DIM + col];
                    acc.x += v0.x; acc.y += v0.y; acc.z += v0.z; acc.w += v0.w;
                }
            }
        }

        if (datal) {
            float4 vs = *(const float4*)&g_hw[(size_t)node * DIM + col];
            acc.x += vs.x; acc.y += vs.y; acc.z += vs.z; acc.w += vs.w;

            float dd = g_dis[node];
            float4 r;
            r.x = fmaf(acc.x, dd, b4.x);
            r.y = fmaf(acc.y, dd, b4.y);
            r.z = fmaf(acc.z, dd, b4.z);
            r.w = fmaf(acc.w, dd, b4.w);
            *(float4*)&g_agg[(size_t)node * DIM + col] = r;

            st.x += r.x; st.y += r.y; st.z += r.z; st.w += r.w;
            sq.x = fmaf(r.x, r.x, sq.x); sq.y = fmaf(r.y, r.y, sq.y);
            sq.z = fmaf(r.z, r.z, sq.z); sq.w = fmaf(r.w, r.w, sq.w);
        }
    }
    if (datal) {
        atomicAdd(&ssum[col + 0], st.x); atomicAdd(&ssum[col + 1], st.y);
        atomicAdd(&ssum[col + 2], st.z); atomicAdd(&ssum[col + 3], st.w);
        atomicAdd(&ssq[col + 0], sq.x);  atomicAdd(&ssq[col + 1], sq.y);
        atomicAdd(&ssq[col + 2], sq.z);  atomicAdd(&ssq[col + 3], sq.w);
    }
    __syncthreads();
    // striped global stats: copy chosen by low block bits -> 8x less contention
    {
        float* sbase = &g_stats8[(blockIdx.x & (STATS_COPIES - 1)) * STATS_STRIDE];
        if (t < DIM) {
            atomicAdd(&sbase[t], ssum[t]);
            atomicAdd(&sbase[256 + t], ssq[t]);
        }
    }

    // ---- last-block BN finalize ----
    __threadfence();
    __syncthreads();
    if (t == 0) {
        unsigned v = atomicAdd(&g_done, 1u);
        s_last = (v == (unsigned)(gridDim.x - 1));
    }
    __syncthreads();
    if (s_last) {
        if (t < DIM) {
            float s = 0.0f, s2 = 0.0f;
#pragma unroll
            for (int cp = 0; cp < STATS_COPIES; cp++) {
                s  += atomicAdd(&g_stats8[cp * STATS_STRIDE + t], 0.0f);
                s2 += atomicAdd(&g_stats8[cp * STATS_STRIDE + 256 + t], 0.0f);
            }
            float mu  = s * (1.0f / N_NODES);
            float var = s2 * (1.0f / N_NODES) - mu * mu;
            float rs  = rsqrtf(var + BN_EPS);
            float a   = rs * gamma[t];
            g_bn[t] = a;
            g_bn[DIM + t] = beta[t] - mu * a;
            // reset all copies (each address touched by exactly one thread;
            // kernel boundary publishes before next layer's gather)
#pragma unroll
            for (int cp = 0; cp < STATS_COPIES; cp++) {
                g_stats8[cp * STATS_STRIDE + t] = 0.0f;
                g_stats8[cp * STATS_STRIDE + 256 + t] = 0.0f;
            }
        }
        if (t == 0) g_done = 0;
    }
}

// ---------------- pooling (champion, unchanged) ----------------
__global__ __launch_bounds__(384) void pool_kernel(const int* __restrict__ batch,
                                                   float* __restrict__ out) {
    int c = threadIdx.x;
    int ty = threadIdx.y;
    int r0 = blockIdx.x * 128;
    int rend = r0 + 128; if (rend > N_NODES) rend = N_NODES;
    float a = g_bn[c], cc = g_bn[DIM + c];
    float acc = 0.0f;
    int cg = -1;
    for (int r = r0 + ty; r < rend; r += 4) {
        float v = fmaxf(fmaf(g_agg[(size_t)r * DIM + c], a, cc), 0.0f);
        int g = batch[r];
        if (g != cg) {
            if (cg >= 0) atomicAdd(&out[cg * DIM + c], acc);
            cg = g; acc = 0.0f;
        }
        acc += v;
    }
    if (cg >= 0) atomicAdd(&out[cg * DIM + c], acc);
}

__global__ void pool_div_kernel(float* __restrict__ out) {
    int i = blockIdx.x * blockDim.x + threadIdx.x;
    if (i < N_GRAPHS * DIM) {
        float cnt = g_cnt[i / DIM];
        out[i] = out[i] / fmaxf(cnt, 1.0f);
    }
}

// ---------------- launch (champion structure) ----------------
extern "C" void kernel_launch(void* const* d_in, const int* in_sizes, int n_in,
                              void* d_out, int out_size) {
    const float* x     = (const float*)d_in[0];
    const int*   eidx  = (const int*)d_in[1];
    const int*   batch = (const int*)d_in[2];
    const float* W     = (const float*)d_in[3];
    const float* b     = (const float*)d_in[4];
    const float* gamma = (const float*)d_in[5];
    const float* beta  = (const float*)d_in[6];
    float* out = (float*)d_out;

    const int* src = eidx;
    const int* dst = eidx + N_EDGES;

    static cudaStream_t s1 = nullptr;
    static cudaEvent_t ev_a = nullptr, ev_csr = nullptr;
    static uint32_t* bfrag_ptr = nullptr;
    if (!s1) {
        cudaFuncSetAttribute(mma_gemm_kernel,
                             cudaFuncAttributeMaxDynamicSharedMemorySize, MMA_SMEM);
        cudaStreamCreateWithFlags(&s1, cudaStreamNonBlocking);
        cudaEventCreateWithFlags(&ev_a, cudaEventDisableTiming);
        cudaEventCreateWithFlags(&ev_csr, cudaEventDisableTiming);
        cudaGetSymbolAddress((void**)&bfrag_ptr, g_bfrag);
    }

    // main stream: bfrag pack + init + deg + scanA (dis needed by gemm epilogue)
    bfrag_pack_kernel<<<(N_LAYERS * BFRAG_PER_LAYER + 255) / 256, 256>>>(W);
    init_kernel<<<(N_NODES + 255) / 256, 256>>>(out);
    deg_kernel<<<512, 256>>>(dst, batch);
    scanA_kernel<<<SCAN_BLOCKS, 256>>>();
    cudaEventRecord(ev_a, 0);

    // side stream: finish CSR build, overlapped with layer-0 GEMM
    cudaStreamWaitEvent(s1, ev_a, 0);
    scanB_kernel<<<1, 256, 0, s1>>>();
    scanC_kernel<<<SCAN_BLOCKS, 256, 0, s1>>>();
    csr_fill_kernel<<<(N_EDGES + 255) / 256, 256, 0, s1>>>(src, dst);
    cudaEventRecord(ev_csr, s1);

    int gemm_grid = (N_NODES + 127) / 128;   // 391

    mma_gemm_kernel<<<gemm_grid, 256, MMA_SMEM>>>(x, bfrag_ptr, 0);
    cudaStreamWaitEvent(0, ev_csr, 0);

    for (int l = 0; l < N_LAYERS; l++) {
        if (l > 0)
            mma_gemm_kernel<<<gemm_grid, 256, MMA_SMEM>>>(
                x, bfrag_ptr + l * BFRAG_PER_LAYER, 1);
        gather_kernel<<<GATHER_BLOCKS, 256>>>(b + l * DIM, gamma + l * DIM,
                                              beta + l * DIM);
    }

    dim3 pool_blk(96, 4);
    pool_kernel<<<(N_NODES + 127) / 128, pool_blk>>>(batch, out);
    pool_div_kernel<<<(N_GRAPHS * DIM + 255) / 256, 256>>>(out);
}